// round 9
// baseline (speedup 1.0000x reference)
#include <cuda_runtime.h>
#include <cuda_bf16.h>
#include <math.h>
#include <cstdint>

// Problem constants
#define BB 2
#define TT 2048
#define CC 1024
#define HH 16
#define DD 64
#define MM (BB*TT)   // 4096

// ---------------------------------------------------------------------------
// Scratch (allocation-free: __device__ globals)
// ---------------------------------------------------------------------------
__device__ float g_q[MM*CC];
__device__ float g_k[MM*CC];
__device__ float g_v[MM*CC];
__device__ float g_att[MM*CC];

// ---------------------------------------------------------------------------
// mma.sync helpers (sm_100 base target: HMMA path, no tcgen05)
// ---------------------------------------------------------------------------
__device__ __forceinline__ uint32_t f2tf(float f) {
    uint32_t u;
    asm("cvt.rna.tf32.f32 %0, %1;" : "=r"(u) : "f"(f));
    return u;
}

__device__ __forceinline__ void mma_tf32(float* d, const uint32_t* a, const uint32_t* b) {
    asm volatile(
        "mma.sync.aligned.m16n8k8.row.col.f32.tf32.tf32.f32 "
        "{%0,%1,%2,%3}, {%4,%5,%6,%7}, {%8,%9}, {%0,%1,%2,%3};"
        : "+f"(d[0]), "+f"(d[1]), "+f"(d[2]), "+f"(d[3])
        : "r"(a[0]), "r"(a[1]), "r"(a[2]), "r"(a[3]),
          "r"(b[0]), "r"(b[1]));
}

__device__ __forceinline__ uint32_t smem_u32(const void* p) {
    uint32_t a;
    asm("{ .reg .u64 t; cvta.to.shared.u64 t, %1; cvt.u32.u64 %0, t; }"
        : "=r"(a) : "l"(p));
    return a;
}

__device__ __forceinline__ void cp_async16(uint32_t dst, const void* src) {
    asm volatile("cp.async.ca.shared.global [%0], [%1], 16;" :: "r"(dst), "l"(src));
}

__device__ __forceinline__ void cp_async16_cg(uint32_t dst, const void* src) {
    asm volatile("cp.async.cg.shared.global [%0], [%1], 16;" :: "r"(dst), "l"(src));
}

// ===========================================================================
// tf32 mma.sync GEMM core:  C[M,N] = A[M,K] @ W[N,K]^T + bias[N]
// CTA tile 128x128, BK=16, 256 threads = 8 warps (2M x 4N), warp tile 64x32.
// 3-stage cp.async pipeline (dynamic smem), wait_group 1 at loop top:
// each tile's loads get ~2 compute blocks of latency cover.
// cvt.rna.tf32 at fragment load (bit-identical to store-side conversion).
// ===========================================================================
#define GBK 16
#define BKP 20
#define NKT (CC / GBK)      // 64
#define GSTG 3
#define STG_U32 (128 * BKP)                    // uint32 per array per stage
#define GEMM_SMEM_BYTES (GSTG * 2 * STG_U32 * 4)   // 61440

__device__ __forceinline__ void gemm_mma_body(
    const float* __restrict__ A, const float* __restrict__ W,
    const float* __restrict__ bias, float* __restrict__ C,
    int m0, int n0, uint32_t* sm)
{
    const int tid = threadIdx.x;
    const int wid = tid >> 5;
    const int lane = tid & 31;
    const int g  = lane >> 2;
    const int tg = lane & 3;
    const int warp_m = wid >> 2;
    const int warp_n = wid & 3;
    const float* Ag = A + (size_t)m0 * CC;
    const float* Wg = W + (size_t)n0 * CC;

    uint32_t* Asm[GSTG];
    uint32_t* Wsm[GSTG];
    uint32_t  sAu[GSTG], sWu[GSTG];
    #pragma unroll
    for (int s = 0; s < GSTG; s++) {
        Asm[s] = sm + s * STG_U32;
        Wsm[s] = sm + (GSTG + s) * STG_U32;
        sAu[s] = smem_u32(Asm[s]);
        sWu[s] = smem_u32(Wsm[s]);
    }

    float d[4][4][4];
    #pragma unroll
    for (int mt = 0; mt < 4; mt++)
        #pragma unroll
        for (int nt = 0; nt < 4; nt++)
            #pragma unroll
            for (int r = 0; r < 4; r++) d[mt][nt][r] = 0.f;

    const int r0 = tid >> 2;          // 0..63 : rows r0 and r0+64
    const int c0 = (tid & 3) * 4;     // 0,4,8,12
    const uint32_t so0 = (uint32_t)(r0 * BKP + c0) * 4u;
    const uint32_t so1 = (uint32_t)((r0 + 64) * BKP + c0) * 4u;

    // preload kt = 0, 1
    #pragma unroll
    for (int p = 0; p < 2; p++) {
        const int koff = p * GBK;
        cp_async16_cg(sAu[p] + so0, Ag + (size_t)r0 * CC + koff + c0);
        cp_async16_cg(sAu[p] + so1, Ag + (size_t)(r0 + 64) * CC + koff + c0);
        cp_async16_cg(sWu[p] + so0, Wg + (size_t)r0 * CC + koff + c0);
        cp_async16_cg(sWu[p] + so1, Wg + (size_t)(r0 + 64) * CC + koff + c0);
        asm volatile("cp.async.commit_group;");
    }

    int buf = 0;
    for (int kt = 0; kt < NKT; kt++) {
        asm volatile("cp.async.wait_group 1;");   // oldest group (tile kt) done
        __syncthreads();   // buf visible to all; readers of (kt-1)'s buf done

        if (kt + 2 < NKT) {
            const int koff = (kt + 2) * GBK;
            const int nb = (buf + 2 >= GSTG) ? buf + 2 - GSTG : buf + 2;
            cp_async16_cg(sAu[nb] + so0, Ag + (size_t)r0 * CC + koff + c0);
            cp_async16_cg(sAu[nb] + so1, Ag + (size_t)(r0 + 64) * CC + koff + c0);
            cp_async16_cg(sWu[nb] + so0, Wg + (size_t)r0 * CC + koff + c0);
            cp_async16_cg(sWu[nb] + so1, Wg + (size_t)(r0 + 64) * CC + koff + c0);
            asm volatile("cp.async.commit_group;");
        } else {
            // keep group-count bookkeeping uniform
            asm volatile("cp.async.commit_group;");
        }

        const uint32_t* Ab = Asm[buf];
        const uint32_t* Wb = Wsm[buf];
        #pragma unroll
        for (int ks = 0; ks < 2; ks++) {
            const int k0 = ks * 8;
            uint32_t af[4][4], bf[4][2];
            #pragma unroll
            for (int mt = 0; mt < 4; mt++) {
                const int row = warp_m * 64 + mt * 16 + g;
                const uint32_t* p  = &Ab[row * BKP + k0 + tg];
                const uint32_t* p8 = p + 8 * BKP;
                af[mt][0] = f2tf(__uint_as_float(p[0]));
                af[mt][1] = f2tf(__uint_as_float(p8[0]));
                af[mt][2] = f2tf(__uint_as_float(p[4]));
                af[mt][3] = f2tf(__uint_as_float(p8[4]));
            }
            #pragma unroll
            for (int nt = 0; nt < 4; nt++) {
                const int rn = warp_n * 32 + nt * 8 + g;
                const uint32_t* p = &Wb[rn * BKP + k0 + tg];
                bf[nt][0] = f2tf(__uint_as_float(p[0]));
                bf[nt][1] = f2tf(__uint_as_float(p[4]));
            }
            #pragma unroll
            for (int mt = 0; mt < 4; mt++)
                #pragma unroll
                for (int nt = 0; nt < 4; nt++)
                    mma_tf32(d[mt][nt], af[mt], bf[nt]);
        }
        buf = (buf + 1 >= GSTG) ? 0 : buf + 1;
    }

    #pragma unroll
    for (int mt = 0; mt < 4; mt++) {
        const int row = m0 + warp_m * 64 + mt * 16 + g;
        #pragma unroll
        for (int nt = 0; nt < 4; nt++) {
            const int col = n0 + warp_n * 32 + nt * 8 + tg * 2;
            float2 bv = *reinterpret_cast<const float2*>(bias + col);
            float2 o0 = make_float2(d[mt][nt][0] + bv.x, d[mt][nt][1] + bv.y);
            float2 o1 = make_float2(d[mt][nt][2] + bv.x, d[mt][nt][3] + bv.y);
            *reinterpret_cast<float2*>(C + (size_t)row * CC + col) = o0;
            *reinterpret_cast<float2*>(C + (size_t)(row + 8) * CC + col) = o1;
        }
    }
}

// Single-matrix GEMM (output projection)
__global__ __launch_bounds__(256) void gemm_mma_kernel(
    const float* __restrict__ A, const float* __restrict__ W,
    const float* __restrict__ bias, float* __restrict__ C)
{
    extern __shared__ __align__(16) uint32_t smg[];
    gemm_mma_body(A, W, bias, C, blockIdx.y * 128, blockIdx.x * 128, smg);
}

// Fused QKV projection: blockIdx.z selects {Wq,bq,q} / {Wk,bk,k} / {Wv,bv,v}
__global__ __launch_bounds__(256) void gemm_qkv_kernel(
    const float* __restrict__ x,
    const float* __restrict__ Wq, const float* __restrict__ bq, float* __restrict__ q,
    const float* __restrict__ Wk, const float* __restrict__ bk, float* __restrict__ k,
    const float* __restrict__ Wv, const float* __restrict__ bv, float* __restrict__ v)
{
    extern __shared__ __align__(16) uint32_t smg[];
    const float* W; const float* b; float* C;
    if (blockIdx.z == 0)      { W = Wq; b = bq; C = q; }
    else if (blockIdx.z == 1) { W = Wk; b = bk; C = k; }
    else                      { W = Wv; b = bv; C = v; }
    gemm_mma_body(x, W, b, C, blockIdx.y * 128, blockIdx.x * 128, smg);
}

// ===========================================================================
// Tensor-core flash attention (causal), tf32 mma.sync.   (unchanged R6-R8)
// CTA: 128 q rows, 8 warps (16 q rows/warp), kv tile 64, D=64.
// grid = (T/128, H, B) = (16, 16, 2), 256 threads.
// qt REVERSED vs blockIdx.x so heaviest blocks schedule first.
// ===========================================================================
#define AQ 128
#define AKV 64
#define KP 68               // K/Q smem row pad (floats): bank = 4g+tg (bijective)
#define VP 72               // V   smem row pad (floats): bank = 8tg+g (bijective)
#define SM_K0 0
#define SM_K1 (64*KP)
#define SM_V0 (2*64*KP)
#define SM_V1 (2*64*KP + 64*VP)
#define ATT_SMEM_BYTES ((2*64*KP + 2*64*VP) * 4)   // 71680

__global__ __launch_bounds__(256, 2) void attention_mma_kernel(
    const float* __restrict__ Qg, const float* __restrict__ Kg,
    const float* __restrict__ Vg, float* __restrict__ Og)
{
    extern __shared__ __align__(16) float smf[];
    const uint32_t sbase = smem_u32(smf);
    const int tid = threadIdx.x;
    const int w = tid >> 5;
    const int lane = tid & 31;
    const int g = lane >> 2, tg = lane & 3;
    const int qt = gridDim.x - 1 - blockIdx.x;   // heavy blocks first
    const int h = blockIdx.y, b = blockIdx.z;
    const int q0 = qt * AQ;
    const size_t bh = (size_t)b * TT * CC + (size_t)h * DD;  // + t*CC + d

    // --- stage Q (scaled by 1/sqrt(D)) into smem [128][KP] ---
    {
        const float sc = 0.125f;
        #pragma unroll
        for (int j = 0; j < 8; j++) {
            int idx = tid + j * 256;           // 0..2047
            int r = idx >> 4, cc = (idx & 15) * 4;
            float4 val = *reinterpret_cast<const float4*>(
                Qg + bh + (size_t)(q0 + r) * CC + cc);
            float* dst = smf + r * KP + cc;
            dst[0] = val.x * sc; dst[1] = val.y * sc;
            dst[2] = val.z * sc; dst[3] = val.w * sc;
        }
    }
    __syncthreads();

    // --- Q A-fragments to registers (persist whole kernel) ---
    uint32_t qa[8][4];
    {
        const uint32_t* Qs = reinterpret_cast<const uint32_t*>(smf);
        const int r0 = (w * 16 + g) * KP;
        #pragma unroll
        for (int kk = 0; kk < 8; kk++) {
            qa[kk][0] = Qs[r0 + kk * 8 + tg];
            qa[kk][1] = Qs[r0 + 8 * KP + kk * 8 + tg];
            qa[kk][2] = Qs[r0 + kk * 8 + tg + 4];
            qa[kk][3] = Qs[r0 + 8 * KP + kk * 8 + tg + 4];
        }
    }
    __syncthreads();   // Q stage area becomes K buffers

    float s[8][4], oo[8][4];
    float m0 = -1e30f, m1 = -1e30f, l0 = 0.f, l1 = 0.f;
    #pragma unroll
    for (int nt = 0; nt < 8; nt++) {
        oo[nt][0] = oo[nt][1] = oo[nt][2] = oo[nt][3] = 0.f;
    }

    const int ntiles = 2 * qt + 2;
    const int wrow_first = q0 + w * 16;
    const int wrow_last  = wrow_first + 15;

    const uint32_t kbuf_b[2] = { sbase + SM_K0 * 4u, sbase + SM_K1 * 4u };
    const uint32_t vbuf_b[2] = { sbase + SM_V0 * 4u, sbase + SM_V1 * 4u };

    // preload tile 0
    #pragma unroll
    for (int j = 0; j < 4; j++) {
        int idx = tid + j * 256;               // 0..1023
        int r = idx >> 4, cc = (idx & 15) * 4;
        const float* srcK = Kg + bh + (size_t)r * CC + cc;
        const float* srcV = Vg + bh + (size_t)r * CC + cc;
        cp_async16(kbuf_b[0] + (uint32_t)(r * KP + cc) * 4u, srcK);
        cp_async16(vbuf_b[0] + (uint32_t)(r * VP + cc) * 4u, srcV);
    }
    asm volatile("cp.async.commit_group;");
    asm volatile("cp.async.wait_group 0;");
    __syncthreads();

    for (int t = 0; t < ntiles; t++) {
        const int buf = t & 1;
        if (t + 1 < ntiles) {
            const int kv0n = (t + 1) * AKV;
            #pragma unroll
            for (int j = 0; j < 4; j++) {
                int idx = tid + j * 256;
                int r = idx >> 4, cc = (idx & 15) * 4;
                const float* srcK = Kg + bh + (size_t)(kv0n + r) * CC + cc;
                const float* srcV = Vg + bh + (size_t)(kv0n + r) * CC + cc;
                cp_async16(kbuf_b[buf ^ 1] + (uint32_t)(r * KP + cc) * 4u, srcK);
                cp_async16(vbuf_b[buf ^ 1] + (uint32_t)(r * VP + cc) * 4u, srcV);
            }
            asm volatile("cp.async.commit_group;");
        }

        const int kv0 = t * AKV;
        if (kv0 <= wrow_last) {   // warp has at least one unmasked element
            const uint32_t* Ks = reinterpret_cast<const uint32_t*>(smf)
                                 + (buf ? SM_K1 : SM_K0);
            const uint32_t* Vs = reinterpret_cast<const uint32_t*>(smf)
                                 + (buf ? SM_V1 : SM_V0);
            // ---- S = Q K^T ----
            #pragma unroll
            for (int nt = 0; nt < 8; nt++) {
                s[nt][0] = s[nt][1] = s[nt][2] = s[nt][3] = 0.f;
            }
            #pragma unroll
            for (int nt = 0; nt < 8; nt++) {
                const int rb = (nt * 8 + g) * KP;
                #pragma unroll
                for (int kk = 0; kk < 8; kk++) {
                    uint32_t bb[2] = { Ks[rb + kk * 8 + tg], Ks[rb + kk * 8 + tg + 4] };
                    mma_tf32(s[nt], qa[kk], bb);
                }
            }
            // ---- causal mask (diagonal tiles only) ----
            if (kv0 + AKV - 1 > wrow_first) {
                const int r0a = wrow_first + g, r1a = r0a + 8;
                #pragma unroll
                for (int nt = 0; nt < 8; nt++) {
                    const int c = kv0 + nt * 8 + 2 * tg;
                    if (c     > r0a) s[nt][0] = -1e30f;
                    if (c + 1 > r0a) s[nt][1] = -1e30f;
                    if (c     > r1a) s[nt][2] = -1e30f;
                    if (c + 1 > r1a) s[nt][3] = -1e30f;
                }
            }
            // ---- online softmax (register-resident) ----
            float mx0 = m0, mx1 = m1;
            #pragma unroll
            for (int nt = 0; nt < 8; nt++) {
                mx0 = fmaxf(mx0, fmaxf(s[nt][0], s[nt][1]));
                mx1 = fmaxf(mx1, fmaxf(s[nt][2], s[nt][3]));
            }
            mx0 = fmaxf(mx0, __shfl_xor_sync(0xffffffffu, mx0, 1));
            mx0 = fmaxf(mx0, __shfl_xor_sync(0xffffffffu, mx0, 2));
            mx1 = fmaxf(mx1, __shfl_xor_sync(0xffffffffu, mx1, 1));
            mx1 = fmaxf(mx1, __shfl_xor_sync(0xffffffffu, mx1, 2));
            const float al0 = __expf(m0 - mx0), al1 = __expf(m1 - mx1);
            m0 = mx0; m1 = mx1;
            float sum0 = 0.f, sum1 = 0.f;
            #pragma unroll
            for (int nt = 0; nt < 8; nt++) {
                s[nt][0] = __expf(s[nt][0] - mx0); sum0 += s[nt][0];
                s[nt][1] = __expf(s[nt][1] - mx0); sum0 += s[nt][1];
                s[nt][2] = __expf(s[nt][2] - mx1); sum1 += s[nt][2];
                s[nt][3] = __expf(s[nt][3] - mx1); sum1 += s[nt][3];
            }
            l0 = l0 * al0 + sum0;
            l1 = l1 * al1 + sum1;
            #pragma unroll
            for (int nt = 0; nt < 8; nt++) {
                oo[nt][0] *= al0; oo[nt][1] *= al0;
                oo[nt][2] *= al1; oo[nt][3] *= al1;
            }
            // ---- P (C-frag) -> A-frag via shuffles, in place ----
            const int base = lane & ~3;
            #pragma unroll
            for (int kk = 0; kk < 8; kk++) {
                const int srcA = base | (tg >> 1);
                const int srcB = srcA + 2;
                float x0 = __shfl_sync(0xffffffffu, s[kk][0], srcA);
                float x1 = __shfl_sync(0xffffffffu, s[kk][1], srcA);
                float x2 = __shfl_sync(0xffffffffu, s[kk][2], srcA);
                float x3 = __shfl_sync(0xffffffffu, s[kk][3], srcA);
                float y0 = __shfl_sync(0xffffffffu, s[kk][0], srcB);
                float y1 = __shfl_sync(0xffffffffu, s[kk][1], srcB);
                float y2 = __shfl_sync(0xffffffffu, s[kk][2], srcB);
                float y3 = __shfl_sync(0xffffffffu, s[kk][3], srcB);
                const bool odd = tg & 1;
                s[kk][0] = odd ? x1 : x0;   // a0: row g,   col tg
                s[kk][1] = odd ? x3 : x2;   // a1: row g+8, col tg
                s[kk][2] = odd ? y1 : y0;   // a2: row g,   col tg+4
                s[kk][3] = odd ? y3 : y2;   // a3: row g+8, col tg+4
            }
            // ---- O += P V ----
            #pragma unroll
            for (int nt = 0; nt < 8; nt++) {
                #pragma unroll
                for (int kk = 0; kk < 8; kk++) {
                    uint32_t bb[2] = { Vs[(kk * 8 + tg) * VP + nt * 8 + g],
                                       Vs[(kk * 8 + tg + 4) * VP + nt * 8 + g] };
                    mma_tf32(oo[nt], reinterpret_cast<uint32_t*>(s[kk]), bb);
                }
            }
        }
        if (t + 1 < ntiles) asm volatile("cp.async.wait_group 0;");
        __syncthreads();
    }

    // ---- finalize: reduce l over the quad, normalize, store ----
    l0 += __shfl_xor_sync(0xffffffffu, l0, 1);
    l0 += __shfl_xor_sync(0xffffffffu, l0, 2);
    l1 += __shfl_xor_sync(0xffffffffu, l1, 1);
    l1 += __shfl_xor_sync(0xffffffffu, l1, 2);
    const float inv0 = 1.f / l0, inv1 = 1.f / l1;
    const int r0a = q0 + w * 16 + g, r1a = r0a + 8;
    #pragma unroll
    for (int nt = 0; nt < 8; nt++) {
        const int c = nt * 8 + 2 * tg;
        *reinterpret_cast<float2*>(Og + bh + (size_t)r0a * CC + c) =
            make_float2(oo[nt][0] * inv0, oo[nt][1] * inv0);
        *reinterpret_cast<float2*>(Og + bh + (size_t)r1a * CC + c) =
            make_float2(oo[nt][2] * inv1, oo[nt][3] * inv1);
    }
}

// ---------------------------------------------------------------------------
// Launch
// ---------------------------------------------------------------------------
extern "C" void kernel_launch(void* const* d_in, const int* in_sizes, int n_in,
                              void* d_out, int out_size)
{
    const float* x  = (const float*)d_in[0];
    const float* Wq = (const float*)d_in[1];
    const float* bq = (const float*)d_in[2];
    const float* Wk = (const float*)d_in[3];
    const float* bk = (const float*)d_in[4];
    const float* Wv = (const float*)d_in[5];
    const float* bv = (const float*)d_in[6];
    const float* Wo = (const float*)d_in[7];
    const float* bo = (const float*)d_in[8];
    float* out = (float*)d_out;

    float *qp, *kp, *vp, *ap;
    cudaGetSymbolAddress((void**)&qp, g_q);
    cudaGetSymbolAddress((void**)&kp, g_k);
    cudaGetSymbolAddress((void**)&vp, g_v);
    cudaGetSymbolAddress((void**)&ap, g_att);

    cudaFuncSetAttribute(gemm_qkv_kernel,
                         cudaFuncAttributeMaxDynamicSharedMemorySize,
                         GEMM_SMEM_BYTES);
    cudaFuncSetAttribute(gemm_mma_kernel,
                         cudaFuncAttributeMaxDynamicSharedMemorySize,
                         GEMM_SMEM_BYTES);

    // Fused QKV projection: one launch, 768 CTAs
    gemm_qkv_kernel<<<dim3(CC / 128, MM / 128, 3), 256, GEMM_SMEM_BYTES>>>(
        x, Wq, bq, qp, Wk, bk, kp, Wv, bv, vp);

    cudaFuncSetAttribute(attention_mma_kernel,
                         cudaFuncAttributeMaxDynamicSharedMemorySize,
                         ATT_SMEM_BYTES);
    attention_mma_kernel<<<dim3(TT / AQ, HH, BB), 256, ATT_SMEM_BYTES>>>(
        qp, kp, vp, ap);

    gemm_mma_kernel<<<dim3(CC / 128, MM / 128), 256, GEMM_SMEM_BYTES>>>(
        ap, Wo, bo, out);
}

// round 10
// speedup vs baseline: 1.1917x; 1.1917x over previous
#include <cuda_runtime.h>
#include <cuda_bf16.h>
#include <math.h>
#include <cstdint>

// Problem constants
#define BB 2
#define TT 2048
#define CC 1024
#define HH 16
#define DD 64
#define MM (BB*TT)   // 4096

// ---------------------------------------------------------------------------
// Scratch (allocation-free: __device__ globals)
// ---------------------------------------------------------------------------
__device__ float g_q[MM*CC];
__device__ float g_k[MM*CC];
__device__ float g_v[MM*CC];
__device__ float g_att[MM*CC];

// ---------------------------------------------------------------------------
// mma.sync helpers (sm_100 base target: HMMA path, no tcgen05)
// ---------------------------------------------------------------------------
__device__ __forceinline__ uint32_t f2tf(float f) {
    uint32_t u;
    asm("cvt.rna.tf32.f32 %0, %1;" : "=r"(u) : "f"(f));
    return u;
}

__device__ __forceinline__ void mma_tf32(float* d, const uint32_t* a, const uint32_t* b) {
    asm volatile(
        "mma.sync.aligned.m16n8k8.row.col.f32.tf32.tf32.f32 "
        "{%0,%1,%2,%3}, {%4,%5,%6,%7}, {%8,%9}, {%0,%1,%2,%3};"
        : "+f"(d[0]), "+f"(d[1]), "+f"(d[2]), "+f"(d[3])
        : "r"(a[0]), "r"(a[1]), "r"(a[2]), "r"(a[3]),
          "r"(b[0]), "r"(b[1]));
}

__device__ __forceinline__ uint32_t smem_u32(const void* p) {
    uint32_t a;
    asm("{ .reg .u64 t; cvta.to.shared.u64 t, %1; cvt.u32.u64 %0, t; }"
        : "=r"(a) : "l"(p));
    return a;
}

__device__ __forceinline__ void cp_async16(uint32_t dst, const void* src) {
    asm volatile("cp.async.ca.shared.global [%0], [%1], 16;" :: "r"(dst), "l"(src));
}

__device__ __forceinline__ void cp_async16_cg(uint32_t dst, const void* src) {
    asm volatile("cp.async.cg.shared.global [%0], [%1], 16;" :: "r"(dst), "l"(src));
}

// ===========================================================================
// tf32 mma.sync GEMM core:  C[M,N] = A[M,K] @ W[N,K]^T + bias[N]
// CTA tile 128x128, BK=16, 256 threads = 8 warps (2M x 4N), warp tile 64x32.
// 4-stage cp.async ring, k-loop unrolled by 4 -> ALL stage indices are
// compile-time constants (no dynamic smem indexing, unlike the failed R9).
// wait_group 2 at body top => ~3 compute blocks of latency cover per tile.
// cvt.rna.tf32 at fragment load (bit-identical to store-side conversion).
// ===========================================================================
#define GBK 16
#define BKP 20
#define NKT (CC / GBK)      // 64  (divisible by 4)
#define GSTG 4
#define STG_U32 (128 * BKP)                        // uint32 per array per stage
#define GEMM_SMEM_BYTES (GSTG * 2 * STG_U32 * 4)   // 81920

__device__ __forceinline__ void gemm_mma_body(
    const float* __restrict__ A, const float* __restrict__ W,
    const float* __restrict__ bias, float* __restrict__ C,
    int m0, int n0, uint32_t* sm)
{
    const int tid = threadIdx.x;
    const int wid = tid >> 5;
    const int lane = tid & 31;
    const int g  = lane >> 2;
    const int tg = lane & 3;
    const int warp_m = wid >> 2;
    const int warp_n = wid & 3;
    const float* Ag = A + (size_t)m0 * CC;
    const float* Wg = W + (size_t)n0 * CC;

    // Stage s: A at sm + s*STG_U32, W at sm + (GSTG+s)*STG_U32
    const uint32_t sbase = smem_u32(sm);

    float d[4][4][4];
    #pragma unroll
    for (int mt = 0; mt < 4; mt++)
        #pragma unroll
        for (int nt = 0; nt < 4; nt++)
            #pragma unroll
            for (int r = 0; r < 4; r++) d[mt][nt][r] = 0.f;

    const int r0 = tid >> 2;          // 0..63 : rows r0 and r0+64
    const int c0 = (tid & 3) * 4;     // 0,4,8,12
    const uint32_t so0 = (uint32_t)(r0 * BKP + c0) * 4u;
    const uint32_t so1 = (uint32_t)((r0 + 64) * BKP + c0) * 4u;

    // preload tiles 0,1,2 into stages 0,1,2 (one commit group each)
    #pragma unroll
    for (int p = 0; p < 3; p++) {
        const int koff = p * GBK;
        const uint32_t aB = sbase + (uint32_t)(p * STG_U32) * 4u;
        const uint32_t wB = sbase + (uint32_t)((GSTG + p) * STG_U32) * 4u;
        cp_async16_cg(aB + so0, Ag + (size_t)r0 * CC + koff + c0);
        cp_async16_cg(aB + so1, Ag + (size_t)(r0 + 64) * CC + koff + c0);
        cp_async16_cg(wB + so0, Wg + (size_t)r0 * CC + koff + c0);
        cp_async16_cg(wB + so1, Wg + (size_t)(r0 + 64) * CC + koff + c0);
        asm volatile("cp.async.commit_group;");
    }

    for (int kt = 0; kt < NKT; kt += GSTG) {
        #pragma unroll
        for (int u = 0; u < GSTG; u++) {
            // oldest outstanding group (tile kt+u) complete
            asm volatile("cp.async.wait_group 2;");
            __syncthreads();   // stage u visible; readers of stage (u+3)&3 done

            const int pf = kt + u + 3;
            if (pf < NKT) {
                const int ps = (u + 3) & 3;          // compile-time constant
                const int koff = pf * GBK;
                const uint32_t aB = sbase + (uint32_t)(ps * STG_U32) * 4u;
                const uint32_t wB = sbase + (uint32_t)((GSTG + ps) * STG_U32) * 4u;
                cp_async16_cg(aB + so0, Ag + (size_t)r0 * CC + koff + c0);
                cp_async16_cg(aB + so1, Ag + (size_t)(r0 + 64) * CC + koff + c0);
                cp_async16_cg(wB + so0, Wg + (size_t)r0 * CC + koff + c0);
                cp_async16_cg(wB + so1, Wg + (size_t)(r0 + 64) * CC + koff + c0);
            }
            asm volatile("cp.async.commit_group;");  // uniform group count

            const uint32_t* Ab = sm + u * STG_U32;          // constant index
            const uint32_t* Wb = sm + (GSTG + u) * STG_U32; // constant index
            #pragma unroll
            for (int ks = 0; ks < 2; ks++) {
                const int k0 = ks * 8;
                uint32_t af[4][4], bf[4][2];
                #pragma unroll
                for (int mt = 0; mt < 4; mt++) {
                    const int row = warp_m * 64 + mt * 16 + g;
                    const uint32_t* p  = &Ab[row * BKP + k0 + tg];
                    const uint32_t* p8 = p + 8 * BKP;
                    af[mt][0] = f2tf(__uint_as_float(p[0]));
                    af[mt][1] = f2tf(__uint_as_float(p8[0]));
                    af[mt][2] = f2tf(__uint_as_float(p[4]));
                    af[mt][3] = f2tf(__uint_as_float(p8[4]));
                }
                #pragma unroll
                for (int nt = 0; nt < 4; nt++) {
                    const int rn = warp_n * 32 + nt * 8 + g;
                    const uint32_t* p = &Wb[rn * BKP + k0 + tg];
                    bf[nt][0] = f2tf(__uint_as_float(p[0]));
                    bf[nt][1] = f2tf(__uint_as_float(p[4]));
                }
                #pragma unroll
                for (int mt = 0; mt < 4; mt++)
                    #pragma unroll
                    for (int nt = 0; nt < 4; nt++)
                        mma_tf32(d[mt][nt], af[mt], bf[nt]);
            }
        }
    }

    #pragma unroll
    for (int mt = 0; mt < 4; mt++) {
        const int row = m0 + warp_m * 64 + mt * 16 + g;
        #pragma unroll
        for (int nt = 0; nt < 4; nt++) {
            const int col = n0 + warp_n * 32 + nt * 8 + tg * 2;
            float2 bv = *reinterpret_cast<const float2*>(bias + col);
            float2 o0 = make_float2(d[mt][nt][0] + bv.x, d[mt][nt][1] + bv.y);
            float2 o1 = make_float2(d[mt][nt][2] + bv.x, d[mt][nt][3] + bv.y);
            *reinterpret_cast<float2*>(C + (size_t)row * CC + col) = o0;
            *reinterpret_cast<float2*>(C + (size_t)(row + 8) * CC + col) = o1;
        }
    }
}

// Single-matrix GEMM (output projection)
__global__ __launch_bounds__(256) void gemm_mma_kernel(
    const float* __restrict__ A, const float* __restrict__ W,
    const float* __restrict__ bias, float* __restrict__ C)
{
    extern __shared__ __align__(16) uint32_t smg[];
    gemm_mma_body(A, W, bias, C, blockIdx.y * 128, blockIdx.x * 128, smg);
}

// Fused QKV projection: blockIdx.z selects {Wq,bq,q} / {Wk,bk,k} / {Wv,bv,v}
__global__ __launch_bounds__(256) void gemm_qkv_kernel(
    const float* __restrict__ x,
    const float* __restrict__ Wq, const float* __restrict__ bq, float* __restrict__ q,
    const float* __restrict__ Wk, const float* __restrict__ bk, float* __restrict__ k,
    const float* __restrict__ Wv, const float* __restrict__ bv, float* __restrict__ v)
{
    extern __shared__ __align__(16) uint32_t smg[];
    const float* W; const float* b; float* C;
    if (blockIdx.z == 0)      { W = Wq; b = bq; C = q; }
    else if (blockIdx.z == 1) { W = Wk; b = bk; C = k; }
    else                      { W = Wv; b = bv; C = v; }
    gemm_mma_body(x, W, b, C, blockIdx.y * 128, blockIdx.x * 128, smg);
}

// ===========================================================================
// Tensor-core flash attention (causal), tf32 mma.sync.   (unchanged R6-R8)
// CTA: 128 q rows, 8 warps (16 q rows/warp), kv tile 64, D=64.
// grid = (T/128, H, B) = (16, 16, 2), 256 threads.
// qt REVERSED vs blockIdx.x so heaviest blocks schedule first.
// ===========================================================================
#define AQ 128
#define AKV 64
#define KP 68               // K/Q smem row pad (floats): bank = 4g+tg (bijective)
#define VP 72               // V   smem row pad (floats): bank = 8tg+g (bijective)
#define SM_K0 0
#define SM_K1 (64*KP)
#define SM_V0 (2*64*KP)
#define SM_V1 (2*64*KP + 64*VP)
#define ATT_SMEM_BYTES ((2*64*KP + 2*64*VP) * 4)   // 71680

__global__ __launch_bounds__(256, 2) void attention_mma_kernel(
    const float* __restrict__ Qg, const float* __restrict__ Kg,
    const float* __restrict__ Vg, float* __restrict__ Og)
{
    extern __shared__ __align__(16) float smf[];
    const uint32_t sbase = smem_u32(smf);
    const int tid = threadIdx.x;
    const int w = tid >> 5;
    const int lane = tid & 31;
    const int g = lane >> 2, tg = lane & 3;
    const int qt = gridDim.x - 1 - blockIdx.x;   // heavy blocks first
    const int h = blockIdx.y, b = blockIdx.z;
    const int q0 = qt * AQ;
    const size_t bh = (size_t)b * TT * CC + (size_t)h * DD;  // + t*CC + d

    // --- stage Q (scaled by 1/sqrt(D)) into smem [128][KP] ---
    {
        const float sc = 0.125f;
        #pragma unroll
        for (int j = 0; j < 8; j++) {
            int idx = tid + j * 256;           // 0..2047
            int r = idx >> 4, cc = (idx & 15) * 4;
            float4 val = *reinterpret_cast<const float4*>(
                Qg + bh + (size_t)(q0 + r) * CC + cc);
            float* dst = smf + r * KP + cc;
            dst[0] = val.x * sc; dst[1] = val.y * sc;
            dst[2] = val.z * sc; dst[3] = val.w * sc;
        }
    }
    __syncthreads();

    // --- Q A-fragments to registers (persist whole kernel) ---
    uint32_t qa[8][4];
    {
        const uint32_t* Qs = reinterpret_cast<const uint32_t*>(smf);
        const int r0 = (w * 16 + g) * KP;
        #pragma unroll
        for (int kk = 0; kk < 8; kk++) {
            qa[kk][0] = Qs[r0 + kk * 8 + tg];
            qa[kk][1] = Qs[r0 + 8 * KP + kk * 8 + tg];
            qa[kk][2] = Qs[r0 + kk * 8 + tg + 4];
            qa[kk][3] = Qs[r0 + 8 * KP + kk * 8 + tg + 4];
        }
    }
    __syncthreads();   // Q stage area becomes K buffers

    float s[8][4], oo[8][4];
    float m0 = -1e30f, m1 = -1e30f, l0 = 0.f, l1 = 0.f;
    #pragma unroll
    for (int nt = 0; nt < 8; nt++) {
        oo[nt][0] = oo[nt][1] = oo[nt][2] = oo[nt][3] = 0.f;
    }

    const int ntiles = 2 * qt + 2;
    const int wrow_first = q0 + w * 16;
    const int wrow_last  = wrow_first + 15;

    const uint32_t kbuf_b[2] = { sbase + SM_K0 * 4u, sbase + SM_K1 * 4u };
    const uint32_t vbuf_b[2] = { sbase + SM_V0 * 4u, sbase + SM_V1 * 4u };

    // preload tile 0
    #pragma unroll
    for (int j = 0; j < 4; j++) {
        int idx = tid + j * 256;               // 0..1023
        int r = idx >> 4, cc = (idx & 15) * 4;
        const float* srcK = Kg + bh + (size_t)r * CC + cc;
        const float* srcV = Vg + bh + (size_t)r * CC + cc;
        cp_async16(kbuf_b[0] + (uint32_t)(r * KP + cc) * 4u, srcK);
        cp_async16(vbuf_b[0] + (uint32_t)(r * VP + cc) * 4u, srcV);
    }
    asm volatile("cp.async.commit_group;");
    asm volatile("cp.async.wait_group 0;");
    __syncthreads();

    for (int t = 0; t < ntiles; t++) {
        const int buf = t & 1;
        if (t + 1 < ntiles) {
            const int kv0n = (t + 1) * AKV;
            #pragma unroll
            for (int j = 0; j < 4; j++) {
                int idx = tid + j * 256;
                int r = idx >> 4, cc = (idx & 15) * 4;
                const float* srcK = Kg + bh + (size_t)(kv0n + r) * CC + cc;
                const float* srcV = Vg + bh + (size_t)(kv0n + r) * CC + cc;
                cp_async16(kbuf_b[buf ^ 1] + (uint32_t)(r * KP + cc) * 4u, srcK);
                cp_async16(vbuf_b[buf ^ 1] + (uint32_t)(r * VP + cc) * 4u, srcV);
            }
            asm volatile("cp.async.commit_group;");
        }

        const int kv0 = t * AKV;
        if (kv0 <= wrow_last) {   // warp has at least one unmasked element
            const uint32_t* Ks = reinterpret_cast<const uint32_t*>(smf)
                                 + (buf ? SM_K1 : SM_K0);
            const uint32_t* Vs = reinterpret_cast<const uint32_t*>(smf)
                                 + (buf ? SM_V1 : SM_V0);
            // ---- S = Q K^T ----
            #pragma unroll
            for (int nt = 0; nt < 8; nt++) {
                s[nt][0] = s[nt][1] = s[nt][2] = s[nt][3] = 0.f;
            }
            #pragma unroll
            for (int nt = 0; nt < 8; nt++) {
                const int rb = (nt * 8 + g) * KP;
                #pragma unroll
                for (int kk = 0; kk < 8; kk++) {
                    uint32_t bb[2] = { Ks[rb + kk * 8 + tg], Ks[rb + kk * 8 + tg + 4] };
                    mma_tf32(s[nt], qa[kk], bb);
                }
            }
            // ---- causal mask (diagonal tiles only) ----
            if (kv0 + AKV - 1 > wrow_first) {
                const int r0a = wrow_first + g, r1a = r0a + 8;
                #pragma unroll
                for (int nt = 0; nt < 8; nt++) {
                    const int c = kv0 + nt * 8 + 2 * tg;
                    if (c     > r0a) s[nt][0] = -1e30f;
                    if (c + 1 > r0a) s[nt][1] = -1e30f;
                    if (c     > r1a) s[nt][2] = -1e30f;
                    if (c + 1 > r1a) s[nt][3] = -1e30f;
                }
            }
            // ---- online softmax (register-resident) ----
            float mx0 = m0, mx1 = m1;
            #pragma unroll
            for (int nt = 0; nt < 8; nt++) {
                mx0 = fmaxf(mx0, fmaxf(s[nt][0], s[nt][1]));
                mx1 = fmaxf(mx1, fmaxf(s[nt][2], s[nt][3]));
            }
            mx0 = fmaxf(mx0, __shfl_xor_sync(0xffffffffu, mx0, 1));
            mx0 = fmaxf(mx0, __shfl_xor_sync(0xffffffffu, mx0, 2));
            mx1 = fmaxf(mx1, __shfl_xor_sync(0xffffffffu, mx1, 1));
            mx1 = fmaxf(mx1, __shfl_xor_sync(0xffffffffu, mx1, 2));
            const float al0 = __expf(m0 - mx0), al1 = __expf(m1 - mx1);
            m0 = mx0; m1 = mx1;
            float sum0 = 0.f, sum1 = 0.f;
            #pragma unroll
            for (int nt = 0; nt < 8; nt++) {
                s[nt][0] = __expf(s[nt][0] - mx0); sum0 += s[nt][0];
                s[nt][1] = __expf(s[nt][1] - mx0); sum0 += s[nt][1];
                s[nt][2] = __expf(s[nt][2] - mx1); sum1 += s[nt][2];
                s[nt][3] = __expf(s[nt][3] - mx1); sum1 += s[nt][3];
            }
            l0 = l0 * al0 + sum0;
            l1 = l1 * al1 + sum1;
            #pragma unroll
            for (int nt = 0; nt < 8; nt++) {
                oo[nt][0] *= al0; oo[nt][1] *= al0;
                oo[nt][2] *= al1; oo[nt][3] *= al1;
            }
            // ---- P (C-frag) -> A-frag via shuffles, in place ----
            const int base = lane & ~3;
            #pragma unroll
            for (int kk = 0; kk < 8; kk++) {
                const int srcA = base | (tg >> 1);
                const int srcB = srcA + 2;
                float x0 = __shfl_sync(0xffffffffu, s[kk][0], srcA);
                float x1 = __shfl_sync(0xffffffffu, s[kk][1], srcA);
                float x2 = __shfl_sync(0xffffffffu, s[kk][2], srcA);
                float x3 = __shfl_sync(0xffffffffu, s[kk][3], srcA);
                float y0 = __shfl_sync(0xffffffffu, s[kk][0], srcB);
                float y1 = __shfl_sync(0xffffffffu, s[kk][1], srcB);
                float y2 = __shfl_sync(0xffffffffu, s[kk][2], srcB);
                float y3 = __shfl_sync(0xffffffffu, s[kk][3], srcB);
                const bool odd = tg & 1;
                s[kk][0] = odd ? x1 : x0;   // a0: row g,   col tg
                s[kk][1] = odd ? x3 : x2;   // a1: row g+8, col tg
                s[kk][2] = odd ? y1 : y0;   // a2: row g,   col tg+4
                s[kk][3] = odd ? y3 : y2;   // a3: row g+8, col tg+4
            }
            // ---- O += P V ----
            #pragma unroll
            for (int nt = 0; nt < 8; nt++) {
                #pragma unroll
                for (int kk = 0; kk < 8; kk++) {
                    uint32_t bb[2] = { Vs[(kk * 8 + tg) * VP + nt * 8 + g],
                                       Vs[(kk * 8 + tg + 4) * VP + nt * 8 + g] };
                    mma_tf32(oo[nt], reinterpret_cast<uint32_t*>(s[kk]), bb);
                }
            }
        }
        if (t + 1 < ntiles) asm volatile("cp.async.wait_group 0;");
        __syncthreads();
    }

    // ---- finalize: reduce l over the quad, normalize, store ----
    l0 += __shfl_xor_sync(0xffffffffu, l0, 1);
    l0 += __shfl_xor_sync(0xffffffffu, l0, 2);
    l1 += __shfl_xor_sync(0xffffffffu, l1, 1);
    l1 += __shfl_xor_sync(0xffffffffu, l1, 2);
    const float inv0 = 1.f / l0, inv1 = 1.f / l1;
    const int r0a = q0 + w * 16 + g, r1a = r0a + 8;
    #pragma unroll
    for (int nt = 0; nt < 8; nt++) {
        const int c = nt * 8 + 2 * tg;
        *reinterpret_cast<float2*>(Og + bh + (size_t)r0a * CC + c) =
            make_float2(oo[nt][0] * inv0, oo[nt][1] * inv0);
        *reinterpret_cast<float2*>(Og + bh + (size_t)r1a * CC + c) =
            make_float2(oo[nt][2] * inv1, oo[nt][3] * inv1);
    }
}

// ---------------------------------------------------------------------------
// Launch
// ---------------------------------------------------------------------------
extern "C" void kernel_launch(void* const* d_in, const int* in_sizes, int n_in,
                              void* d_out, int out_size)
{
    const float* x  = (const float*)d_in[0];
    const float* Wq = (const float*)d_in[1];
    const float* bq = (const float*)d_in[2];
    const float* Wk = (const float*)d_in[3];
    const float* bk = (const float*)d_in[4];
    const float* Wv = (const float*)d_in[5];
    const float* bv = (const float*)d_in[6];
    const float* Wo = (const float*)d_in[7];
    const float* bo = (const float*)d_in[8];
    float* out = (float*)d_out;

    float *qp, *kp, *vp, *ap;
    cudaGetSymbolAddress((void**)&qp, g_q);
    cudaGetSymbolAddress((void**)&kp, g_k);
    cudaGetSymbolAddress((void**)&vp, g_v);
    cudaGetSymbolAddress((void**)&ap, g_att);

    cudaFuncSetAttribute(gemm_qkv_kernel,
                         cudaFuncAttributeMaxDynamicSharedMemorySize,
                         GEMM_SMEM_BYTES);
    cudaFuncSetAttribute(gemm_mma_kernel,
                         cudaFuncAttributeMaxDynamicSharedMemorySize,
                         GEMM_SMEM_BYTES);

    // Fused QKV projection: one launch, 768 CTAs
    gemm_qkv_kernel<<<dim3(CC / 128, MM / 128, 3), 256, GEMM_SMEM_BYTES>>>(
        x, Wq, bq, qp, Wk, bk, kp, Wv, bv, vp);

    cudaFuncSetAttribute(attention_mma_kernel,
                         cudaFuncAttributeMaxDynamicSharedMemorySize,
                         ATT_SMEM_BYTES);
    attention_mma_kernel<<<dim3(TT / AQ, HH, BB), 256, ATT_SMEM_BYTES>>>(
        qp, kp, vp, ap);

    gemm_mma_kernel<<<dim3(CC / 128, MM / 128), 256, GEMM_SMEM_BYTES>>>(
        ap, Wo, bo, out);
}

// round 12
// speedup vs baseline: 1.3412x; 1.1254x over previous
#include <cuda_runtime.h>
#include <cuda_bf16.h>
#include <math.h>
#include <cstdint>

// Problem constants
#define BB 2
#define TT 2048
#define CC 1024
#define HH 16
#define DD 64
#define MM (BB*TT)   // 4096

// ---------------------------------------------------------------------------
// Scratch (allocation-free: __device__ globals)
// ---------------------------------------------------------------------------
__device__ float g_q[MM*CC];
__device__ float g_k[MM*CC];
__device__ float g_v[MM*CC];
__device__ float g_att[MM*CC];

// ---------------------------------------------------------------------------
// mma.sync helpers (sm_100 base target: HMMA path, no tcgen05)
// ---------------------------------------------------------------------------
__device__ __forceinline__ uint32_t f2tf(float f) {
    uint32_t u;
    asm("cvt.rna.tf32.f32 %0, %1;" : "=r"(u) : "f"(f));
    return u;
}

__device__ __forceinline__ uint32_t f2tf_u(uint32_t x) {
    uint32_t u;
    asm("cvt.rna.tf32.f32 %0, %1;" : "=r"(u) : "f"(__uint_as_float(x)));
    return u;
}

__device__ __forceinline__ void mma_tf32(float* d, const uint32_t* a, const uint32_t* b) {
    asm volatile(
        "mma.sync.aligned.m16n8k8.row.col.f32.tf32.tf32.f32 "
        "{%0,%1,%2,%3}, {%4,%5,%6,%7}, {%8,%9}, {%0,%1,%2,%3};"
        : "+f"(d[0]), "+f"(d[1]), "+f"(d[2]), "+f"(d[3])
        : "r"(a[0]), "r"(a[1]), "r"(a[2]), "r"(a[3]),
          "r"(b[0]), "r"(b[1]));
}

// ldmatrix: four 8x8 b16 tiles == four 8(row)x4(fp32) tiles.
// Thread t receives fp32 element (t%4) of row (t/4) of tile (t/8)... (per-tile
// lane groups: lanes 0-7 supply tile0 row addrs, 8-15 tile1, 16-23 tile2,
// 24-31 tile3; result regs r0..r3 = tiles 0..3).
__device__ __forceinline__ void ldsm_x4(uint32_t& r0, uint32_t& r1,
                                        uint32_t& r2, uint32_t& r3,
                                        uint32_t addr) {
    asm volatile(
        "ldmatrix.sync.aligned.m8n8.x4.shared.b16 {%0,%1,%2,%3}, [%4];"
        : "=r"(r0), "=r"(r1), "=r"(r2), "=r"(r3) : "r"(addr));
}

__device__ __forceinline__ uint32_t smem_u32(const void* p) {
    uint32_t a;
    asm("{ .reg .u64 t; cvta.to.shared.u64 t, %1; cvt.u32.u64 %0, t; }"
        : "=r"(a) : "l"(p));
    return a;
}

__device__ __forceinline__ void cp_async16(uint32_t dst, const void* src) {
    asm volatile("cp.async.ca.shared.global [%0], [%1], 16;" :: "r"(dst), "l"(src));
}

__device__ __forceinline__ void cp_async16_cg(uint32_t dst, const void* src) {
    asm volatile("cp.async.cg.shared.global [%0], [%1], 16;" :: "r"(dst), "l"(src));
}

// ===========================================================================
// tf32 mma.sync GEMM core:  C[M,N] = A[M,K] @ W[N,K]^T + bias[N]
// CTA tile 128x128, BK=16, 256 threads = 8 warps (2M x 4N), warp tile 64x32.
// 4-stage cp.async ring, k-loop unrolled by 4 (constant stage indices).
// Fragment loads via ldmatrix.x4 (LDSM): A = 1 x4 per mt, B = 1 x4 per nt-pair.
// cvt.rna.tf32 applied per register after LDSM (bit-identical numerics).
// ===========================================================================
#define GBK 16
#define BKP 20
#define NKT (CC / GBK)      // 64  (divisible by 4)
#define GSTG 4
#define STG_U32 (128 * BKP)                        // uint32 per array per stage
#define GEMM_SMEM_BYTES (GSTG * 2 * STG_U32 * 4)   // 81920

__device__ __forceinline__ void gemm_mma_body(
    const float* __restrict__ A, const float* __restrict__ W,
    const float* __restrict__ bias, float* __restrict__ C,
    int m0, int n0, uint32_t* sm)
{
    const int tid = threadIdx.x;
    const int wid = tid >> 5;
    const int lane = tid & 31;
    const int g  = lane >> 2;
    const int tg = lane & 3;
    const int warp_m = wid >> 2;
    const int warp_n = wid & 3;
    const float* Ag = A + (size_t)m0 * CC;
    const float* Wg = W + (size_t)n0 * CC;

    const uint32_t sbase = smem_u32(sm);

    // ldmatrix per-lane row/col selectors
    //  A x4 tiles: {rows+0..7 @k0, rows+8..15 @k0, rows+0..7 @k0+4, rows+8 @k0+4}
    const int arow = (lane & 7) + ((lane >> 3) & 1) * 8;
    const int acol = (lane >> 4) * 4;
    //  B x4 tiles: {nt rows @k0, nt rows @k0+4, nt+1 rows @k0, nt+1 rows @k0+4}
    const int brow = (lane & 7) + ((lane >> 4) & 1) * 8;
    const int bcol = ((lane >> 3) & 1) * 4;

    uint32_t aLd[GSTG], bLd[GSTG];
    #pragma unroll
    for (int s = 0; s < GSTG; s++) {
        aLd[s] = sbase + (uint32_t)(s * STG_U32) * 4u
               + (uint32_t)(((warp_m * 64 + arow) * BKP + acol) * 4);
        bLd[s] = sbase + (uint32_t)((GSTG + s) * STG_U32) * 4u
               + (uint32_t)(((warp_n * 32 + brow) * BKP + bcol) * 4);
    }

    float d[4][4][4];
    #pragma unroll
    for (int mt = 0; mt < 4; mt++)
        #pragma unroll
        for (int nt = 0; nt < 4; nt++)
            #pragma unroll
            for (int r = 0; r < 4; r++) d[mt][nt][r] = 0.f;

    const int r0 = tid >> 2;          // 0..63 : rows r0 and r0+64
    const int c0 = (tid & 3) * 4;     // 0,4,8,12
    const uint32_t so0 = (uint32_t)(r0 * BKP + c0) * 4u;
    const uint32_t so1 = (uint32_t)((r0 + 64) * BKP + c0) * 4u;

    // preload tiles 0,1,2 into stages 0,1,2 (one commit group each)
    #pragma unroll
    for (int p = 0; p < 3; p++) {
        const int koff = p * GBK;
        const uint32_t aB = sbase + (uint32_t)(p * STG_U32) * 4u;
        const uint32_t wB = sbase + (uint32_t)((GSTG + p) * STG_U32) * 4u;
        cp_async16_cg(aB + so0, Ag + (size_t)r0 * CC + koff + c0);
        cp_async16_cg(aB + so1, Ag + (size_t)(r0 + 64) * CC + koff + c0);
        cp_async16_cg(wB + so0, Wg + (size_t)r0 * CC + koff + c0);
        cp_async16_cg(wB + so1, Wg + (size_t)(r0 + 64) * CC + koff + c0);
        asm volatile("cp.async.commit_group;");
    }

    for (int kt = 0; kt < NKT; kt += GSTG) {
        #pragma unroll
        for (int u = 0; u < GSTG; u++) {
            // oldest outstanding group (tile kt+u) complete
            asm volatile("cp.async.wait_group 2;");
            __syncthreads();   // stage u visible; readers of stage (u+3)&3 done

            const int pf = kt + u + 3;
            if (pf < NKT) {
                const int ps = (u + 3) & 3;          // compile-time constant
                const int koff = pf * GBK;
                const uint32_t aB = sbase + (uint32_t)(ps * STG_U32) * 4u;
                const uint32_t wB = sbase + (uint32_t)((GSTG + ps) * STG_U32) * 4u;
                cp_async16_cg(aB + so0, Ag + (size_t)r0 * CC + koff + c0);
                cp_async16_cg(aB + so1, Ag + (size_t)(r0 + 64) * CC + koff + c0);
                cp_async16_cg(wB + so0, Wg + (size_t)r0 * CC + koff + c0);
                cp_async16_cg(wB + so1, Wg + (size_t)(r0 + 64) * CC + koff + c0);
            }
            asm volatile("cp.async.commit_group;");  // uniform group count

            const uint32_t aB = aLd[u];              // constant index
            const uint32_t bB = bLd[u];
            #pragma unroll
            for (int ks = 0; ks < 2; ks++) {
                uint32_t af[4][4], bf[2][4];
                #pragma unroll
                for (int mt = 0; mt < 4; mt++) {
                    ldsm_x4(af[mt][0], af[mt][1], af[mt][2], af[mt][3],
                            aB + (uint32_t)((mt * 16 * BKP + ks * 8) * 4));
                }
                #pragma unroll
                for (int np = 0; np < 2; np++) {
                    ldsm_x4(bf[np][0], bf[np][1], bf[np][2], bf[np][3],
                            bB + (uint32_t)((np * 16 * BKP + ks * 8) * 4));
                }
                #pragma unroll
                for (int mt = 0; mt < 4; mt++)
                    #pragma unroll
                    for (int i = 0; i < 4; i++)
                        af[mt][i] = f2tf_u(af[mt][i]);
                #pragma unroll
                for (int np = 0; np < 2; np++)
                    #pragma unroll
                    for (int i = 0; i < 4; i++)
                        bf[np][i] = f2tf_u(bf[np][i]);
                #pragma unroll
                for (int mt = 0; mt < 4; mt++)
                    #pragma unroll
                    for (int nt = 0; nt < 4; nt++)
                        mma_tf32(d[mt][nt], af[mt], &bf[nt >> 1][(nt & 1) * 2]);
            }
        }
    }

    #pragma unroll
    for (int mt = 0; mt < 4; mt++) {
        const int row = m0 + warp_m * 64 + mt * 16 + g;
        #pragma unroll
        for (int nt = 0; nt < 4; nt++) {
            const int col = n0 + warp_n * 32 + nt * 8 + tg * 2;
            float2 bv = *reinterpret_cast<const float2*>(bias + col);
            float2 o0 = make_float2(d[mt][nt][0] + bv.x, d[mt][nt][1] + bv.y);
            float2 o1 = make_float2(d[mt][nt][2] + bv.x, d[mt][nt][3] + bv.y);
            *reinterpret_cast<float2*>(C + (size_t)row * CC + col) = o0;
            *reinterpret_cast<float2*>(C + (size_t)(row + 8) * CC + col) = o1;
        }
    }
}

// Single-matrix GEMM (output projection)
__global__ __launch_bounds__(256) void gemm_mma_kernel(
    const float* __restrict__ A, const float* __restrict__ W,
    const float* __restrict__ bias, float* __restrict__ C)
{
    extern __shared__ __align__(16) uint32_t smg[];
    gemm_mma_body(A, W, bias, C, blockIdx.y * 128, blockIdx.x * 128, smg);
}

// Fused QKV projection: blockIdx.z selects {Wq,bq,q} / {Wk,bk,k} / {Wv,bv,v}
__global__ __launch_bounds__(256) void gemm_qkv_kernel(
    const float* __restrict__ x,
    const float* __restrict__ Wq, const float* __restrict__ bq, float* __restrict__ q,
    const float* __restrict__ Wk, const float* __restrict__ bk, float* __restrict__ k,
    const float* __restrict__ Wv, const float* __restrict__ bv, float* __restrict__ v)
{
    extern __shared__ __align__(16) uint32_t smg[];
    const float* W; const float* b; float* C;
    if (blockIdx.z == 0)      { W = Wq; b = bq; C = q; }
    else if (blockIdx.z == 1) { W = Wk; b = bk; C = k; }
    else                      { W = Wv; b = bv; C = v; }
    gemm_mma_body(x, W, b, C, blockIdx.y * 128, blockIdx.x * 128, smg);
}

// ===========================================================================
// Tensor-core flash attention (causal), tf32 mma.sync.
// CTA: 128 q rows, 8 warps (16 q rows/warp), kv tile 64, D=64.
// grid = (T/128, H, B) = (16, 16, 2), 256 threads.
// K fragments via ldmatrix.x4 (4 fragments / 2 MMAs per LDSM); V scalar.
// qt REVERSED vs blockIdx.x so heaviest blocks schedule first.
// ===========================================================================
#define AQ 128
#define AKV 64
#define KP 68               // K/Q smem row pad (floats): conflict-free
#define VP 72               // V   smem row pad (floats): conflict-free
#define SM_K0 0
#define SM_K1 (64*KP)
#define SM_V0 (2*64*KP)
#define SM_V1 (2*64*KP + 64*VP)
#define ATT_SMEM_BYTES ((2*64*KP + 2*64*VP) * 4)   // 71680

__global__ __launch_bounds__(256, 2) void attention_mma_kernel(
    const float* __restrict__ Qg, const float* __restrict__ Kg,
    const float* __restrict__ Vg, float* __restrict__ Og)
{
    extern __shared__ __align__(16) float smf[];
    const uint32_t sbase = smem_u32(smf);
    const int tid = threadIdx.x;
    const int w = tid >> 5;
    const int lane = tid & 31;
    const int g = lane >> 2, tg = lane & 3;
    const int qt = gridDim.x - 1 - blockIdx.x;   // heavy blocks first
    const int h = blockIdx.y, b = blockIdx.z;
    const int q0 = qt * AQ;
    const size_t bh = (size_t)b * TT * CC + (size_t)h * DD;  // + t*CC + d

    // --- stage Q (scaled by 1/sqrt(D)) into smem [128][KP] ---
    {
        const float sc = 0.125f;
        #pragma unroll
        for (int j = 0; j < 8; j++) {
            int idx = tid + j * 256;           // 0..2047
            int r = idx >> 4, cc = (idx & 15) * 4;
            float4 val = *reinterpret_cast<const float4*>(
                Qg + bh + (size_t)(q0 + r) * CC + cc);
            float* dst = smf + r * KP + cc;
            dst[0] = val.x * sc; dst[1] = val.y * sc;
            dst[2] = val.z * sc; dst[3] = val.w * sc;
        }
    }
    __syncthreads();

    // --- Q A-fragments to registers (persist whole kernel) ---
    uint32_t qa[8][4];
    {
        const uint32_t* Qs = reinterpret_cast<const uint32_t*>(smf);
        const int r0 = (w * 16 + g) * KP;
        #pragma unroll
        for (int kk = 0; kk < 8; kk++) {
            qa[kk][0] = Qs[r0 + kk * 8 + tg];
            qa[kk][1] = Qs[r0 + 8 * KP + kk * 8 + tg];
            qa[kk][2] = Qs[r0 + kk * 8 + tg + 4];
            qa[kk][3] = Qs[r0 + 8 * KP + kk * 8 + tg + 4];
        }
    }
    __syncthreads();   // Q stage area becomes K buffers

    float s[8][4], oo[8][4];
    float m0 = -1e30f, m1 = -1e30f, l0 = 0.f, l1 = 0.f;
    #pragma unroll
    for (int nt = 0; nt < 8; nt++) {
        oo[nt][0] = oo[nt][1] = oo[nt][2] = oo[nt][3] = 0.f;
    }

    const int ntiles = 2 * qt + 2;
    const int wrow_first = q0 + w * 16;
    const int wrow_last  = wrow_first + 15;

    const uint32_t kbuf_b[2] = { sbase + SM_K0 * 4u, sbase + SM_K1 * 4u };
    const uint32_t vbuf_b[2] = { sbase + SM_V0 * 4u, sbase + SM_V1 * 4u };

    // K ldmatrix per-lane selectors: x4 tiles at col offsets 0,4,8,12 from base,
    // all tiles share rows nt*8 + (lane&7).
    const int krow = lane & 7;
    const int kcol = (lane >> 3) * 4;
    const uint32_t kLd[2] = {
        kbuf_b[0] + (uint32_t)((krow * KP + kcol) * 4),
        kbuf_b[1] + (uint32_t)((krow * KP + kcol) * 4)
    };

    // preload tile 0
    #pragma unroll
    for (int j = 0; j < 4; j++) {
        int idx = tid + j * 256;               // 0..1023
        int r = idx >> 4, cc = (idx & 15) * 4;
        const float* srcK = Kg + bh + (size_t)r * CC + cc;
        const float* srcV = Vg + bh + (size_t)r * CC + cc;
        cp_async16(kbuf_b[0] + (uint32_t)(r * KP + cc) * 4u, srcK);
        cp_async16(vbuf_b[0] + (uint32_t)(r * VP + cc) * 4u, srcV);
    }
    asm volatile("cp.async.commit_group;");
    asm volatile("cp.async.wait_group 0;");
    __syncthreads();

    for (int t = 0; t < ntiles; t++) {
        const int buf = t & 1;
        if (t + 1 < ntiles) {
            const int kv0n = (t + 1) * AKV;
            #pragma unroll
            for (int j = 0; j < 4; j++) {
                int idx = tid + j * 256;
                int r = idx >> 4, cc = (idx & 15) * 4;
                const float* srcK = Kg + bh + (size_t)(kv0n + r) * CC + cc;
                const float* srcV = Vg + bh + (size_t)(kv0n + r) * CC + cc;
                cp_async16(kbuf_b[buf ^ 1] + (uint32_t)(r * KP + cc) * 4u, srcK);
                cp_async16(vbuf_b[buf ^ 1] + (uint32_t)(r * VP + cc) * 4u, srcV);
            }
            asm volatile("cp.async.commit_group;");
        }

        const int kv0 = t * AKV;
        if (kv0 <= wrow_last) {   // warp has at least one unmasked element
            const uint32_t kB = kLd[buf];
            const uint32_t* Vs = reinterpret_cast<const uint32_t*>(smf)
                                 + (buf ? SM_V1 : SM_V0);
            // ---- S = Q K^T (K fragments via ldmatrix.x4) ----
            #pragma unroll
            for (int nt = 0; nt < 8; nt++) {
                s[nt][0] = s[nt][1] = s[nt][2] = s[nt][3] = 0.f;
            }
            #pragma unroll
            for (int nt = 0; nt < 8; nt++) {
                #pragma unroll
                for (int kkp = 0; kkp < 4; kkp++) {
                    uint32_t kb[4];
                    ldsm_x4(kb[0], kb[1], kb[2], kb[3],
                            kB + (uint32_t)((nt * 8 * KP + kkp * 16) * 4));
                    mma_tf32(s[nt], qa[2 * kkp],     &kb[0]);
                    mma_tf32(s[nt], qa[2 * kkp + 1], &kb[2]);
                }
            }
            // ---- causal mask (diagonal tiles only) ----
            if (kv0 + AKV - 1 > wrow_first) {
                const int r0a = wrow_first + g, r1a = r0a + 8;
                #pragma unroll
                for (int nt = 0; nt < 8; nt++) {
                    const int c = kv0 + nt * 8 + 2 * tg;
                    if (c     > r0a) s[nt][0] = -1e30f;
                    if (c + 1 > r0a) s[nt][1] = -1e30f;
                    if (c     > r1a) s[nt][2] = -1e30f;
                    if (c + 1 > r1a) s[nt][3] = -1e30f;
                }
            }
            // ---- online softmax (register-resident) ----
            float mx0 = m0, mx1 = m1;
            #pragma unroll
            for (int nt = 0; nt < 8; nt++) {
                mx0 = fmaxf(mx0, fmaxf(s[nt][0], s[nt][1]));
                mx1 = fmaxf(mx1, fmaxf(s[nt][2], s[nt][3]));
            }
            mx0 = fmaxf(mx0, __shfl_xor_sync(0xffffffffu, mx0, 1));
            mx0 = fmaxf(mx0, __shfl_xor_sync(0xffffffffu, mx0, 2));
            mx1 = fmaxf(mx1, __shfl_xor_sync(0xffffffffu, mx1, 1));
            mx1 = fmaxf(mx1, __shfl_xor_sync(0xffffffffu, mx1, 2));
            const float al0 = __expf(m0 - mx0), al1 = __expf(m1 - mx1);
            m0 = mx0; m1 = mx1;
            float sum0 = 0.f, sum1 = 0.f;
            #pragma unroll
            for (int nt = 0; nt < 8; nt++) {
                s[nt][0] = __expf(s[nt][0] - mx0); sum0 += s[nt][0];
                s[nt][1] = __expf(s[nt][1] - mx0); sum0 += s[nt][1];
                s[nt][2] = __expf(s[nt][2] - mx1); sum1 += s[nt][2];
                s[nt][3] = __expf(s[nt][3] - mx1); sum1 += s[nt][3];
            }
            l0 = l0 * al0 + sum0;
            l1 = l1 * al1 + sum1;
            #pragma unroll
            for (int nt = 0; nt < 8; nt++) {
                oo[nt][0] *= al0; oo[nt][1] *= al0;
                oo[nt][2] *= al1; oo[nt][3] *= al1;
            }
            // ---- P (C-frag) -> A-frag via shuffles, in place ----
            const int base = lane & ~3;
            #pragma unroll
            for (int kk = 0; kk < 8; kk++) {
                const int srcA = base | (tg >> 1);
                const int srcB = srcA + 2;
                float x0 = __shfl_sync(0xffffffffu, s[kk][0], srcA);
                float x1 = __shfl_sync(0xffffffffu, s[kk][1], srcA);
                float x2 = __shfl_sync(0xffffffffu, s[kk][2], srcA);
                float x3 = __shfl_sync(0xffffffffu, s[kk][3], srcA);
                float y0 = __shfl_sync(0xffffffffu, s[kk][0], srcB);
                float y1 = __shfl_sync(0xffffffffu, s[kk][1], srcB);
                float y2 = __shfl_sync(0xffffffffu, s[kk][2], srcB);
                float y3 = __shfl_sync(0xffffffffu, s[kk][3], srcB);
                const bool odd = tg & 1;
                s[kk][0] = odd ? x1 : x0;   // a0: row g,   col tg
                s[kk][1] = odd ? x3 : x2;   // a1: row g+8, col tg
                s[kk][2] = odd ? y1 : y0;   // a2: row g,   col tg+4
                s[kk][3] = odd ? y3 : y2;   // a3: row g+8, col tg+4
            }
            // ---- O += P V ----
            #pragma unroll
            for (int nt = 0; nt < 8; nt++) {
                #pragma unroll
                for (int kk = 0; kk < 8; kk++) {
                    uint32_t bb[2] = { Vs[(kk * 8 + tg) * VP + nt * 8 + g],
                                       Vs[(kk * 8 + tg + 4) * VP + nt * 8 + g] };
                    mma_tf32(oo[nt], reinterpret_cast<uint32_t*>(s[kk]), bb);
                }
            }
        }
        if (t + 1 < ntiles) asm volatile("cp.async.wait_group 0;");
        __syncthreads();
    }

    // ---- finalize: reduce l over the quad, normalize, store ----
    l0 += __shfl_xor_sync(0xffffffffu, l0, 1);
    l0 += __shfl_xor_sync(0xffffffffu, l0, 2);
    l1 += __shfl_xor_sync(0xffffffffu, l1, 1);
    l1 += __shfl_xor_sync(0xffffffffu, l1, 2);
    const float inv0 = 1.f / l0, inv1 = 1.f / l1;
    const int r0a = q0 + w * 16 + g, r1a = r0a + 8;
    #pragma unroll
    for (int nt = 0; nt < 8; nt++) {
        const int c = nt * 8 + 2 * tg;
        *reinterpret_cast<float2*>(Og + bh + (size_t)r0a * CC + c) =
            make_float2(oo[nt][0] * inv0, oo[nt][1] * inv0);
        *reinterpret_cast<float2*>(Og + bh + (size_t)r1a * CC + c) =
            make_float2(oo[nt][2] * inv1, oo[nt][3] * inv1);
    }
}

// ---------------------------------------------------------------------------
// Launch
// ---------------------------------------------------------------------------
extern "C" void kernel_launch(void* const* d_in, const int* in_sizes, int n_in,
                              void* d_out, int out_size)
{
    const float* x  = (const float*)d_in[0];
    const float* Wq = (const float*)d_in[1];
    const float* bq = (const float*)d_in[2];
    const float* Wk = (const float*)d_in[3];
    const float* bk = (const float*)d_in[4];
    const float* Wv = (const float*)d_in[5];
    const float* bv = (const float*)d_in[6];
    const float* Wo = (const float*)d_in[7];
    const float* bo = (const float*)d_in[8];
    float* out = (float*)d_out;

    float *qp, *kp, *vp, *ap;
    cudaGetSymbolAddress((void**)&qp, g_q);
    cudaGetSymbolAddress((void**)&kp, g_k);
    cudaGetSymbolAddress((void**)&vp, g_v);
    cudaGetSymbolAddress((void**)&ap, g_att);

    cudaFuncSetAttribute(gemm_qkv_kernel,
                         cudaFuncAttributeMaxDynamicSharedMemorySize,
                         GEMM_SMEM_BYTES);
    cudaFuncSetAttribute(gemm_mma_kernel,
                         cudaFuncAttributeMaxDynamicSharedMemorySize,
                         GEMM_SMEM_BYTES);

    // Fused QKV projection: one launch, 768 CTAs
    gemm_qkv_kernel<<<dim3(CC / 128, MM / 128, 3), 256, GEMM_SMEM_BYTES>>>(
        x, Wq, bq, qp, Wk, bk, kp, Wv, bv, vp);

    cudaFuncSetAttribute(attention_mma_kernel,
                         cudaFuncAttributeMaxDynamicSharedMemorySize,
                         ATT_SMEM_BYTES);
    attention_mma_kernel<<<dim3(TT / AQ, HH, BB), 256, ATT_SMEM_BYTES>>>(
        qp, kp, vp, ap);

    gemm_mma_kernel<<<dim3(CC / 128, MM / 128), 256, GEMM_SMEM_BYTES>>>(
        ap, Wo, bo, out);
}